// round 2
// baseline (speedup 1.0000x reference)
#include <cuda_runtime.h>
#include <math.h>

#define NN 4096
#define DD 512
#define TT 4096
#define INV_TEMP (1.0f/0.07f)
#define EPSF 1e-8f
#define PD_EPSF 1e-6f
#define MARGINF 0.5f
#define TRIP_W 0.3f

// Scratch (device globals; no dynamic allocation allowed)
__device__ float g_nemb[NN*DD];   // normalized embeddings (8 MB, fits in L2)
__device__ float g_pos[NN];       // per-row sum of exp(sim)*pos_mask
__device__ float g_tot[NN];       // per-row sum of exp(sim)
__device__ float g_trip[TT];      // per-triplet hinge

// ---------------------------------------------------------------------------
// Kernel 1: row-normalize embeddings; also zero the per-row accumulators
// (graph replays must be deterministic -> re-zero every launch).
// grid = NN blocks, 128 threads (D/4 = 128 float4 per row -> 1 per thread)
// ---------------------------------------------------------------------------
__global__ void norm_kernel(const float* __restrict__ emb) {
    int r = blockIdx.x;
    int t = threadIdx.x;
    float4 v = ((const float4*)(emb + (size_t)r * DD))[t];
    float s = v.x*v.x + v.y*v.y + v.z*v.z + v.w*v.w;
    #pragma unroll
    for (int o = 16; o; o >>= 1) s += __shfl_xor_sync(0xffffffffu, s, o);
    __shared__ float ws[4];
    if ((t & 31) == 0) ws[t >> 5] = s;
    __syncthreads();
    float tot = ws[0] + ws[1] + ws[2] + ws[3];
    float inv = 1.0f / fmaxf(sqrtf(tot), EPSF);
    float4 o4 = make_float4(v.x*inv, v.y*inv, v.z*inv, v.w*inv);
    ((float4*)(g_nemb + (size_t)r * DD))[t] = o4;
    if (t == 0) { g_pos[r] = 0.0f; g_tot[r] = 0.0f; }
}

// ---------------------------------------------------------------------------
// Kernel 2: fused  n_emb @ n_emb.T / TEMP -> exp -> masked row sums.
// Classic fp32 SGEMM tiling: BM=BN=128, BK=16, 256 threads, 8x8 micro-tile.
// Epilogue: exp via MUFU, label-mask, half-warp shuffle reduce, atomicAdd.
// grid = (32, 32)
// ---------------------------------------------------------------------------
#define BM 128
#define BN 128
#define BK 16

__global__ __launch_bounds__(256, 2) void sim_kernel(const int* __restrict__ labels) {
    __shared__ float As[BK][BM + 4];
    __shared__ float Bs[BK][BN + 4];
    __shared__ int   lrow[BM];
    __shared__ int   lcol[BN];

    int tid = threadIdx.x;
    int tx = tid & 15, ty = tid >> 4;
    int rb = blockIdx.y * BM, cb = blockIdx.x * BN;

    if (tid < BM) lrow[tid] = labels[rb + tid];
    else          lcol[tid - BM] = labels[cb + tid - BM];

    float acc[8][8];
    #pragma unroll
    for (int i = 0; i < 8; i++)
        #pragma unroll
        for (int j = 0; j < 8; j++) acc[i][j] = 0.0f;

    for (int k0 = 0; k0 < DD; k0 += BK) {
        #pragma unroll
        for (int l = 0; l < 2; l++) {
            int id  = tid + l * 256;     // 0..511
            int row = id >> 2;           // 0..127
            int kk  = (id & 3) << 2;     // 0,4,8,12
            float4 va = *(const float4*)&g_nemb[(size_t)(rb + row) * DD + k0 + kk];
            As[kk+0][row] = va.x; As[kk+1][row] = va.y;
            As[kk+2][row] = va.z; As[kk+3][row] = va.w;
            float4 vb = *(const float4*)&g_nemb[(size_t)(cb + row) * DD + k0 + kk];
            Bs[kk+0][row] = vb.x; Bs[kk+1][row] = vb.y;
            Bs[kk+2][row] = vb.z; Bs[kk+3][row] = vb.w;
        }
        __syncthreads();

        #pragma unroll
        for (int k = 0; k < BK; k++) {
            float a[8], b[8];
            float4 a0 = *(const float4*)&As[k][ty * 8];
            float4 a1 = *(const float4*)&As[k][ty * 8 + 4];
            float4 b0 = *(const float4*)&Bs[k][tx * 8];
            float4 b1 = *(const float4*)&Bs[k][tx * 8 + 4];
            a[0]=a0.x; a[1]=a0.y; a[2]=a0.z; a[3]=a0.w;
            a[4]=a1.x; a[5]=a1.y; a[6]=a1.z; a[7]=a1.w;
            b[0]=b0.x; b[1]=b0.y; b[2]=b0.z; b[3]=b0.w;
            b[4]=b1.x; b[5]=b1.y; b[6]=b1.z; b[7]=b1.w;
            #pragma unroll
            for (int i = 0; i < 8; i++)
                #pragma unroll
                for (int j = 0; j < 8; j++)
                    acc[i][j] = fmaf(a[i], b[j], acc[i][j]);
        }
        __syncthreads();
    }

    // Epilogue: exp + masked per-row partial sums
    float pos[8], tot[8];
    #pragma unroll
    for (int i = 0; i < 8; i++) { pos[i] = 0.0f; tot[i] = 0.0f; }

    #pragma unroll
    for (int i = 0; i < 8; i++) {
        int lr = lrow[ty * 8 + i];
        int Rg = rb + ty * 8 + i;
        #pragma unroll
        for (int j = 0; j < 8; j++) {
            float e = __expf(acc[i][j] * INV_TEMP);
            tot[i] += e;
            int Cg = cb + tx * 8 + j;
            if (lr == lcol[tx * 8 + j] && Rg != Cg) pos[i] += e;
        }
    }

    // Each sim row within the tile is owned by 16 lanes of one half-warp
    // (lanes 0-15 share ty, lanes 16-31 share ty+1) -> width-16 shuffle reduce.
    int lane = tid & 31;
    #pragma unroll
    for (int i = 0; i < 8; i++) {
        float p = pos[i], q = tot[i];
        #pragma unroll
        for (int o = 8; o; o >>= 1) {
            p += __shfl_down_sync(0xffffffffu, p, o, 16);
            q += __shfl_down_sync(0xffffffffu, q, o, 16);
        }
        if ((lane & 15) == 0) {
            int Rg = rb + ty * 8 + i;
            atomicAdd(&g_pos[Rg], p);
            atomicAdd(&g_tot[Rg], q);
        }
    }
}

// ---------------------------------------------------------------------------
// Kernel 3: triplet hinge per triplet. One warp per triplet, 8 warps/block.
// Uses UNNORMALIZED embeddings (matches reference).
// ---------------------------------------------------------------------------
__global__ void trip_kernel(const float* __restrict__ emb,
                            const int* __restrict__ trips) {
    int warp = threadIdx.x >> 5;
    int lane = threadIdx.x & 31;
    int t = blockIdx.x * 8 + warp;
    if (t >= TT) return;
    int ia = trips[3*t + 0], ip = trips[3*t + 1], in_ = trips[3*t + 2];
    const float4* pa = (const float4*)(emb + (size_t)ia * DD);
    const float4* pp = (const float4*)(emb + (size_t)ip * DD);
    const float4* pn = (const float4*)(emb + (size_t)in_ * DD);
    float sp = 0.0f, sn = 0.0f;
    #pragma unroll
    for (int w = 0; w < 4; w++) {
        int idx = lane + w * 32;       // 128 float4 per row
        float4 a = pa[idx], p = pp[idx], n = pn[idx];
        float d;
        d = a.x - p.x + PD_EPSF; sp = fmaf(d, d, sp);
        d = a.y - p.y + PD_EPSF; sp = fmaf(d, d, sp);
        d = a.z - p.z + PD_EPSF; sp = fmaf(d, d, sp);
        d = a.w - p.w + PD_EPSF; sp = fmaf(d, d, sp);
        d = a.x - n.x + PD_EPSF; sn = fmaf(d, d, sn);
        d = a.y - n.y + PD_EPSF; sn = fmaf(d, d, sn);
        d = a.z - n.z + PD_EPSF; sn = fmaf(d, d, sn);
        d = a.w - n.w + PD_EPSF; sn = fmaf(d, d, sn);
    }
    #pragma unroll
    for (int o = 16; o; o >>= 1) {
        sp += __shfl_xor_sync(0xffffffffu, sp, o);
        sn += __shfl_xor_sync(0xffffffffu, sn, o);
    }
    if (lane == 0)
        g_trip[t] = fmaxf(sqrtf(sp) - sqrtf(sn) + MARGINF, 0.0f);
}

// ---------------------------------------------------------------------------
// Kernel 4: finalize. Single block reduces per-row losses + triplet hinges.
// ---------------------------------------------------------------------------
__global__ void fin_kernel(float* __restrict__ out) {
    int tid = threadIdx.x;  // 1024 threads
    float lsum = 0.0f, csum = 0.0f, tsum = 0.0f;
    for (int r = tid; r < NN; r += 1024) {
        float p = g_pos[r], q = g_tot[r];
        if (p > 0.0f) {                     // valid <=> any positive match
            lsum += -logf(p / (q + EPSF) + EPSF);
            csum += 1.0f;
        }
    }
    for (int t = tid; t < TT; t += 1024) tsum += g_trip[t];

    __shared__ float s0[1024], s1[1024], s2[1024];
    s0[tid] = lsum; s1[tid] = csum; s2[tid] = tsum;
    __syncthreads();
    for (int o = 512; o; o >>= 1) {
        if (tid < o) {
            s0[tid] += s0[tid + o];
            s1[tid] += s1[tid + o];
            s2[tid] += s2[tid + o];
        }
        __syncthreads();
    }
    if (tid == 0) {
        float cont = (s1[0] > 0.0f) ? (s0[0] / s1[0]) : 0.0f;
        float trip = s2[0] / (float)TT;
        out[0] = cont + TRIP_W * trip;   // total
        out[1] = cont;                   // cont_loss
        out[2] = trip;                   // trip_loss
    }
}

// ---------------------------------------------------------------------------
extern "C" void kernel_launch(void* const* d_in, const int* in_sizes, int n_in,
                              void* d_out, int out_size) {
    (void)in_sizes; (void)n_in; (void)out_size;
    const float* emb    = (const float*)d_in[0];
    const int*   labels = (const int*)d_in[1];
    const int*   trips  = (const int*)d_in[2];
    float*       out    = (float*)d_out;

    norm_kernel<<<NN, 128>>>(emb);
    sim_kernel<<<dim3(NN / BN, NN / BM), 256>>>(labels);
    trip_kernel<<<TT / 8, 256>>>(emb, trips);
    fin_kernel<<<1, 1024>>>(out);
}

// round 5
// speedup vs baseline: 8.1024x; 8.1024x over previous
#include <cuda_runtime.h>
#include <cuda_bf16.h>
#include <math.h>
#include <cstdint>

#define NN 4096
#define DD 512
#define TT 4096
#define INV_TEMP (1.0f/0.07f)
#define EPSF 1e-8f
#define PD_EPSF 1e-6f
#define MARGINF 0.5f
#define TRIP_W 0.3f

// ---------------- scratch (no dynamic allocation allowed) -----------------
__device__ __nv_bfloat16 g_nembh[NN*DD];  // normalized embeddings, bf16 (4 MB)
__device__ float g_pos[NN];
__device__ float g_tot[NN];
__device__ float g_trip[TT];

__device__ __forceinline__ uint32_t smem_u32(const void* p) {
    uint32_t a;
    asm("{ .reg .u64 t; cvta.to.shared.u64 t, %1; cvt.u32.u64 %0, t; }"
        : "=r"(a) : "l"(p));
    return a;
}

#define SW128(o) ((o) ^ (((o) >> 3) & 0x70))

__device__ __forceinline__ void ldsm_x4(uint32_t* r, uint32_t addr) {
    asm volatile("ldmatrix.sync.aligned.m8n8.x4.shared.b16 {%0,%1,%2,%3}, [%4];"
                 : "=r"(r[0]), "=r"(r[1]), "=r"(r[2]), "=r"(r[3]) : "r"(addr));
}
__device__ __forceinline__ void mma16816(float* c, const uint32_t* a,
                                         uint32_t b0, uint32_t b1) {
    asm volatile(
        "mma.sync.aligned.m16n8k16.row.col.f32.bf16.bf16.f32 "
        "{%0,%1,%2,%3}, {%4,%5,%6,%7}, {%8,%9}, {%0,%1,%2,%3};"
        : "+f"(c[0]), "+f"(c[1]), "+f"(c[2]), "+f"(c[3])
        : "r"(a[0]), "r"(a[1]), "r"(a[2]), "r"(a[3]), "r"(b0), "r"(b1));
}

// ---------------------------------------------------------------------------
// Kernel 1: normalize rows -> bf16; zero accumulators.
// ---------------------------------------------------------------------------
__global__ void norm_kernel(const float* __restrict__ emb) {
    int r = blockIdx.x;
    int t = threadIdx.x;
    float4 v = ((const float4*)(emb + (size_t)r * DD))[t];
    float s = v.x*v.x + v.y*v.y + v.z*v.z + v.w*v.w;
    #pragma unroll
    for (int o = 16; o; o >>= 1) s += __shfl_xor_sync(0xffffffffu, s, o);
    __shared__ float ws[4];
    if ((t & 31) == 0) ws[t >> 5] = s;
    __syncthreads();
    float inv = rsqrtf(fmaxf(ws[0] + ws[1] + ws[2] + ws[3], EPSF * EPSF));
    __nv_bfloat162 lo = __floats2bfloat162_rn(v.x * inv, v.y * inv);
    __nv_bfloat162 hi = __floats2bfloat162_rn(v.z * inv, v.w * inv);
    uint2 u;
    u.x = *(uint32_t*)&lo;
    u.y = *(uint32_t*)&hi;
    ((uint2*)(g_nembh + (size_t)r * DD))[t] = u;
    if (t == 0) { g_pos[r] = 0.0f; g_tot[r] = 0.0f; }
}

// ---------------------------------------------------------------------------
// Kernel 2: bf16 HMMA GEMM (mma.sync m16n8k16) 128x128 tile over K=512
// (8 chunks of 64), fused exp + masked row-sum epilogue from registers.
// grid = (32, 32), 256 threads = 8 warps (4M x 2N), warp tile 32x64.
// ---------------------------------------------------------------------------
#define BK 64
#define NCHUNK (DD / BK)   // 8

__global__ void __launch_bounds__(256) sim_kernel(const int* __restrict__ labels) {
    __shared__ __align__(128) __nv_bfloat16 sA[128 * BK];   // 16 KB
    __shared__ __align__(128) __nv_bfloat16 sB[128 * BK];   // 16 KB
    __shared__ int   s_lcol[128], s_lrow[128];
    __shared__ float s_pos[128], s_tot[128];

    int tid  = threadIdx.x;
    int lane = tid & 31;
    int wid  = tid >> 5;
    int wm   = wid >> 1;     // 0..3 -> M block of 32 rows
    int wn   = wid & 1;      // 0..1 -> N block of 64 cols
    int rb   = blockIdx.y * 128;
    int cb   = blockIdx.x * 128;

    if (tid < 128) {
        s_lcol[tid] = labels[cb + tid];
        s_lrow[tid] = labels[rb + tid];
        s_pos[tid] = 0.0f;
        s_tot[tid] = 0.0f;
    }

    uint32_t baseA = smem_u32(sA), baseB = smem_u32(sB);

    // per-lane ldmatrix base addresses (swizzle folded in; +ks*32 per k-step)
    uint32_t a_addr[2];
    #pragma unroll
    for (int mf = 0; mf < 2; mf++) {
        int row = wm * 32 + mf * 16 + (lane & 15);
        a_addr[mf] = baseA + (uint32_t)((row * 128) ^ ((row & 7) << 4))
                   + ((lane >> 4) << 4);
    }
    uint32_t b_addr[4];
    #pragma unroll
    for (int np = 0; np < 4; np++) {
        int row = wn * 64 + np * 16 + (lane & 7) + ((lane >> 4) << 3);
        b_addr[np] = baseB + (uint32_t)((row * 128) ^ ((row & 7) << 4))
                   + (((lane >> 3) & 1) << 4);
    }

    // global/shared copy indexing: u = tid + 256*i; row=u>>3, seg=u&7 (8 bf16)
    const __nv_bfloat16* gA[4];
    const __nv_bfloat16* gB[4];
    uint32_t stA[4], stB[4];
    #pragma unroll
    for (int i = 0; i < 4; i++) {
        int u = tid + 256 * i;
        int row = u >> 3, seg = u & 7;
        gA[i] = g_nembh + (size_t)(rb + row) * DD + seg * 8;
        gB[i] = g_nembh + (size_t)(cb + row) * DD + seg * 8;
        uint32_t off = SW128((uint32_t)(row * 128 + seg * 16));
        stA[i] = off;   // byte offsets into sA/sB
        stB[i] = off;
    }

    float acc[2][8][4];
    #pragma unroll
    for (int mf = 0; mf < 2; mf++)
        #pragma unroll
        for (int nf = 0; nf < 8; nf++)
            #pragma unroll
            for (int k = 0; k < 4; k++) acc[mf][nf][k] = 0.0f;

    // prologue: chunk 0 -> smem
    uint4 ra[4], rbv[4];
    #pragma unroll
    for (int i = 0; i < 4; i++) { ra[i] = *(const uint4*)gA[i]; rbv[i] = *(const uint4*)gB[i]; }
    #pragma unroll
    for (int i = 0; i < 4; i++) {
        *(uint4*)((char*)sA + stA[i]) = ra[i];
        *(uint4*)((char*)sB + stB[i]) = rbv[i];
    }
    __syncthreads();

    #pragma unroll 1
    for (int c = 0; c < NCHUNK; c++) {
        if (c + 1 < NCHUNK) {
            int k0 = (c + 1) * BK;
            #pragma unroll
            for (int i = 0; i < 4; i++) {
                ra[i]  = *(const uint4*)(gA[i] + k0);
                rbv[i] = *(const uint4*)(gB[i] + k0);
            }
        }
        #pragma unroll
        for (int ks = 0; ks < 4; ks++) {
            uint32_t af[2][4], bf[4][4];
            ldsm_x4(af[0], a_addr[0] + ks * 32);
            ldsm_x4(af[1], a_addr[1] + ks * 32);
            #pragma unroll
            for (int p = 0; p < 4; p++) ldsm_x4(bf[p], b_addr[p] + ks * 32);
            #pragma unroll
            for (int mf = 0; mf < 2; mf++)
                #pragma unroll
                for (int p = 0; p < 4; p++) {
                    mma16816(acc[mf][2 * p],     af[mf], bf[p][0], bf[p][1]);
                    mma16816(acc[mf][2 * p + 1], af[mf], bf[p][2], bf[p][3]);
                }
        }
        __syncthreads();
        if (c + 1 < NCHUNK) {
            #pragma unroll
            for (int i = 0; i < 4; i++) {
                *(uint4*)((char*)sA + stA[i]) = ra[i];
                *(uint4*)((char*)sB + stB[i]) = rbv[i];
            }
            __syncthreads();
        }
    }

    // ---- epilogue: exp + masked row sums from register fragments ----
    const float EXP_DIAG = __expf(INV_TEMP);
    int quad = lane >> 2, qid = lane & 3;
    #pragma unroll
    for (int mf = 0; mf < 2; mf++) {
        #pragma unroll
        for (int h = 0; h < 2; h++) {
            int R  = wm * 32 + mf * 16 + quad + 8 * h;
            int Rg = rb + R;
            int lr = s_lrow[R];
            float p = 0.0f, t = 0.0f;
            #pragma unroll
            for (int nf = 0; nf < 8; nf++) {
                #pragma unroll
                for (int j = 0; j < 2; j++) {
                    int cidx = wn * 64 + nf * 8 + 2 * qid + j;
                    float e = __expf(acc[mf][nf][2 * h + j] * INV_TEMP);
                    if (cb + cidx == Rg) {
                        t += EXP_DIAG;            // exact diagonal
                    } else {
                        t += e;
                        if (s_lcol[cidx] == lr) p += e;
                    }
                }
            }
            p += __shfl_xor_sync(0xffffffffu, p, 1);
            p += __shfl_xor_sync(0xffffffffu, p, 2);
            t += __shfl_xor_sync(0xffffffffu, t, 1);
            t += __shfl_xor_sync(0xffffffffu, t, 2);
            if (qid == 0) {
                atomicAdd(&s_pos[R], p);
                atomicAdd(&s_tot[R], t);
            }
        }
    }
    __syncthreads();
    if (tid < 128) {
        atomicAdd(&g_pos[rb + tid], s_pos[tid]);
        atomicAdd(&g_tot[rb + tid], s_tot[tid]);
    }
}

// ---------------------------------------------------------------------------
// Kernel 3: triplet hinge. One warp per triplet (raw fp32 embeddings).
// ---------------------------------------------------------------------------
__global__ void trip_kernel(const float* __restrict__ emb,
                            const int* __restrict__ trips) {
    int warp = threadIdx.x >> 5;
    int lane = threadIdx.x & 31;
    int t = blockIdx.x * 8 + warp;
    if (t >= TT) return;
    int ia = trips[3*t + 0], ip = trips[3*t + 1], in_ = trips[3*t + 2];
    const float4* pa = (const float4*)(emb + (size_t)ia * DD);
    const float4* pp = (const float4*)(emb + (size_t)ip * DD);
    const float4* pn = (const float4*)(emb + (size_t)in_ * DD);
    float sp = 0.0f, sn = 0.0f;
    #pragma unroll
    for (int w = 0; w < 4; w++) {
        int idx = lane + w * 32;
        float4 a = pa[idx], p = pp[idx], n = pn[idx];
        float d;
        d = a.x - p.x + PD_EPSF; sp = fmaf(d, d, sp);
        d = a.y - p.y + PD_EPSF; sp = fmaf(d, d, sp);
        d = a.z - p.z + PD_EPSF; sp = fmaf(d, d, sp);
        d = a.w - p.w + PD_EPSF; sp = fmaf(d, d, sp);
        d = a.x - n.x + PD_EPSF; sn = fmaf(d, d, sn);
        d = a.y - n.y + PD_EPSF; sn = fmaf(d, d, sn);
        d = a.z - n.z + PD_EPSF; sn = fmaf(d, d, sn);
        d = a.w - n.w + PD_EPSF; sn = fmaf(d, d, sn);
    }
    #pragma unroll
    for (int o = 16; o; o >>= 1) {
        sp += __shfl_xor_sync(0xffffffffu, sp, o);
        sn += __shfl_xor_sync(0xffffffffu, sn, o);
    }
    if (lane == 0)
        g_trip[t] = fmaxf(sqrtf(sp) - sqrtf(sn) + MARGINF, 0.0f);
}

// ---------------------------------------------------------------------------
// Kernel 4: finalize.
// ---------------------------------------------------------------------------
__global__ void fin_kernel(float* __restrict__ out) {
    int tid = threadIdx.x;  // 1024
    float lsum = 0.0f, csum = 0.0f, tsum = 0.0f;
    for (int r = tid; r < NN; r += 1024) {
        float p = g_pos[r], q = g_tot[r];
        if (p > 0.0f) {
            lsum += -__logf(p / (q + EPSF) + EPSF);
            csum += 1.0f;
        }
    }
    for (int t = tid; t < TT; t += 1024) tsum += g_trip[t];

    __shared__ float s0[1024], s1[1024], s2[1024];
    s0[tid] = lsum; s1[tid] = csum; s2[tid] = tsum;
    __syncthreads();
    for (int o = 512; o; o >>= 1) {
        if (tid < o) {
            s0[tid] += s0[tid + o];
            s1[tid] += s1[tid + o];
            s2[tid] += s2[tid + o];
        }
        __syncthreads();
    }
    if (tid == 0) {
        float cont = (s1[0] > 0.0f) ? (s0[0] / s1[0]) : 0.0f;
        float trip = s2[0] / (float)TT;
        out[0] = cont + TRIP_W * trip;
        out[1] = cont;
        out[2] = trip;
    }
}

// ---------------------------------------------------------------------------
extern "C" void kernel_launch(void* const* d_in, const int* in_sizes, int n_in,
                              void* d_out, int out_size) {
    (void)in_sizes; (void)n_in; (void)out_size;
    const float* emb    = (const float*)d_in[0];
    const int*   labels = (const int*)d_in[1];
    const int*   trips  = (const int*)d_in[2];
    float*       out    = (float*)d_out;

    norm_kernel<<<NN, 128>>>(emb);
    sim_kernel<<<dim3(NN / 128, NN / 128), 256>>>(labels);
    trip_kernel<<<TT / 8, 256>>>(emb, trips);
    fin_kernel<<<1, 1024>>>(out);
}

// round 7
// speedup vs baseline: 10.9760x; 1.3547x over previous
#include <cuda_runtime.h>
#include <cuda_bf16.h>
#include <math.h>
#include <cstdint>

#define NN 4096
#define DD 512
#define TT 4096
#define INV_TEMP (1.0f/0.07f)
#define EPSF 1e-8f
#define PD_EPSF 1e-6f
#define MARGINF 0.5f
#define TRIP_W 0.3f
#define NTILE 32                    // 4096/128
#define NTRI  (NTILE*(NTILE+1)/2)   // 528

// ---------------- scratch (no dynamic allocation allowed) -----------------
__device__ __nv_bfloat16 g_nembh[NN*DD];  // normalized embeddings, bf16 (4 MB)
__device__ float g_pos[NN];
__device__ float g_tot[NN];
__device__ float g_fin[4];    // [0]=loss sum, [1]=valid count, [2]=trip sum

__device__ __forceinline__ uint32_t smem_u32(const void* p) {
    uint32_t a;
    asm("{ .reg .u64 t; cvta.to.shared.u64 t, %1; cvt.u32.u64 %0, t; }"
        : "=r"(a) : "l"(p));
    return a;
}

#define SW128(o) ((o) ^ (((o) >> 3) & 0x70))

__device__ __forceinline__ void ldsm_x4(uint32_t* r, uint32_t addr) {
    asm volatile("ldmatrix.sync.aligned.m8n8.x4.shared.b16 {%0,%1,%2,%3}, [%4];"
                 : "=r"(r[0]), "=r"(r[1]), "=r"(r[2]), "=r"(r[3]) : "r"(addr));
}
__device__ __forceinline__ void mma16816(float* c, const uint32_t* a,
                                         uint32_t b0, uint32_t b1) {
    asm volatile(
        "mma.sync.aligned.m16n8k16.row.col.f32.bf16.bf16.f32 "
        "{%0,%1,%2,%3}, {%4,%5,%6,%7}, {%8,%9}, {%0,%1,%2,%3};"
        : "+f"(c[0]), "+f"(c[1]), "+f"(c[2]), "+f"(c[3])
        : "r"(a[0]), "r"(a[1]), "r"(a[2]), "r"(a[3]), "r"(b0), "r"(b1));
}

// ---------------------------------------------------------------------------
// Kernel 1: normalize rows -> bf16; zero accumulators.
// ---------------------------------------------------------------------------
__global__ void norm_kernel(const float* __restrict__ emb) {
    int r = blockIdx.x;
    int t = threadIdx.x;
    float4 v = ((const float4*)(emb + (size_t)r * DD))[t];
    float s = v.x*v.x + v.y*v.y + v.z*v.z + v.w*v.w;
    #pragma unroll
    for (int o = 16; o; o >>= 1) s += __shfl_xor_sync(0xffffffffu, s, o);
    __shared__ float ws[4];
    if ((t & 31) == 0) ws[t >> 5] = s;
    __syncthreads();
    float inv = rsqrtf(fmaxf(ws[0] + ws[1] + ws[2] + ws[3], EPSF * EPSF));
    __nv_bfloat162 lo = __floats2bfloat162_rn(v.x * inv, v.y * inv);
    __nv_bfloat162 hi = __floats2bfloat162_rn(v.z * inv, v.w * inv);
    uint2 u;
    u.x = *(uint32_t*)&lo;
    u.y = *(uint32_t*)&hi;
    ((uint2*)(g_nembh + (size_t)r * DD))[t] = u;
    if (t == 0) {
        g_pos[r] = 0.0f; g_tot[r] = 0.0f;
        if (r == 0) { g_fin[0] = 0.f; g_fin[1] = 0.f; g_fin[2] = 0.f; g_fin[3] = 0.f; }
    }
}

// ---------------------------------------------------------------------------
// Kernel 2: symmetric bf16 HMMA GEMM, upper-triangle 128x128 tiles (528 CTAs).
// Single-buffer smem mainloop (two syncs/chunk — R5-proven structure).
// Off-diagonal tiles scatter exp sums to BOTH row blocks via symmetry.
// 8 warps (4M x 2N), warp tile 32x64, K chunks of 64.
// ---------------------------------------------------------------------------
#define BK 64
#define NCHUNK (DD / BK)   // 8

__global__ void __launch_bounds__(256) sim_kernel(const int* __restrict__ labels) {
    __shared__ __align__(128) __nv_bfloat16 sA[128 * BK];   // 16 KB
    __shared__ __align__(128) __nv_bfloat16 sB[128 * BK];   // 16 KB
    __shared__ int   s_lcol[128], s_lrow[128];
    __shared__ float s_rpos[128], s_rtot[128], s_cpos[128], s_ctot[128];

    int tid  = threadIdx.x;
    int lane = tid & 31;
    int wid  = tid >> 5;
    int wm   = wid >> 1;     // 0..3 -> M block of 32 rows
    int wn   = wid & 1;      // 0..1 -> N block of 64 cols

    // triangular decode: blockIdx.x -> (bi, bj), bi <= bj
    int bi = 0, rem = blockIdx.x;
    while (rem >= NTILE - bi) { rem -= NTILE - bi; bi++; }
    int bj = bi + rem;
    int rb = bi * 128, cb = bj * 128;
    bool diag = (bi == bj);

    if (tid < 128) {
        s_lrow[tid] = labels[rb + tid];
        s_lcol[tid] = labels[cb + tid];
        s_rpos[tid] = 0.0f; s_rtot[tid] = 0.0f;
        s_cpos[tid] = 0.0f; s_ctot[tid] = 0.0f;
    }

    uint32_t baseA = smem_u32(sA), baseB = smem_u32(sB);

    // per-lane ldmatrix base addresses (swizzle folded in; +ks*32 per k-step)
    uint32_t a_addr[2];
    #pragma unroll
    for (int mf = 0; mf < 2; mf++) {
        int row = wm * 32 + mf * 16 + (lane & 15);
        a_addr[mf] = baseA + (uint32_t)((row * 128) ^ ((row & 7) << 4))
                   + ((lane >> 4) << 4);
    }
    uint32_t b_addr[4];
    #pragma unroll
    for (int np = 0; np < 4; np++) {
        int row = wn * 64 + np * 16 + (lane & 7) + ((lane >> 4) << 3);
        b_addr[np] = baseB + (uint32_t)((row * 128) ^ ((row & 7) << 4))
                   + (((lane >> 3) & 1) << 4);
    }

    // global/shared copy indexing: u = tid + 256*i; row=u>>3, seg=u&7 (8 bf16)
    const __nv_bfloat16* gA[4];
    const __nv_bfloat16* gB[4];
    uint32_t stOff[4];
    #pragma unroll
    for (int i = 0; i < 4; i++) {
        int u = tid + 256 * i;
        int row = u >> 3, seg = u & 7;
        gA[i] = g_nembh + (size_t)(rb + row) * DD + seg * 8;
        gB[i] = g_nembh + (size_t)(cb + row) * DD + seg * 8;
        stOff[i] = SW128((uint32_t)(row * 128 + seg * 16));
    }

    float acc[2][8][4];
    #pragma unroll
    for (int mf = 0; mf < 2; mf++)
        #pragma unroll
        for (int nf = 0; nf < 8; nf++)
            #pragma unroll
            for (int k = 0; k < 4; k++) acc[mf][nf][k] = 0.0f;

    // prologue: chunk 0 -> smem
    uint4 ra[4], rbv[4];
    #pragma unroll
    for (int i = 0; i < 4; i++) { ra[i] = *(const uint4*)gA[i]; rbv[i] = *(const uint4*)gB[i]; }
    #pragma unroll
    for (int i = 0; i < 4; i++) {
        *(uint4*)((char*)sA + stOff[i]) = ra[i];
        *(uint4*)((char*)sB + stOff[i]) = rbv[i];
    }
    __syncthreads();

    #pragma unroll 1
    for (int c = 0; c < NCHUNK; c++) {
        if (c + 1 < NCHUNK) {
            int k0 = (c + 1) * BK;
            #pragma unroll
            for (int i = 0; i < 4; i++) {
                ra[i]  = *(const uint4*)(gA[i] + k0);
                rbv[i] = *(const uint4*)(gB[i] + k0);
            }
        }
        #pragma unroll
        for (int ks = 0; ks < 4; ks++) {
            uint32_t af[2][4], bfr[4][4];
            ldsm_x4(af[0], a_addr[0] + ks * 32);
            ldsm_x4(af[1], a_addr[1] + ks * 32);
            #pragma unroll
            for (int p = 0; p < 4; p++) ldsm_x4(bfr[p], b_addr[p] + ks * 32);
            #pragma unroll
            for (int mf = 0; mf < 2; mf++)
                #pragma unroll
                for (int p = 0; p < 4; p++) {
                    mma16816(acc[mf][2 * p],     af[mf], bfr[p][0], bfr[p][1]);
                    mma16816(acc[mf][2 * p + 1], af[mf], bfr[p][2], bfr[p][3]);
                }
        }
        __syncthreads();
        if (c + 1 < NCHUNK) {
            #pragma unroll
            for (int i = 0; i < 4; i++) {
                *(uint4*)((char*)sA + stOff[i]) = ra[i];
                *(uint4*)((char*)sB + stOff[i]) = rbv[i];
            }
            __syncthreads();
        }
    }

    // ---- epilogue ----
    const float EXP_DIAG = __expf(INV_TEMP);
    int quad = lane >> 2, qid = lane & 3;
    int lrv[2][2];

    // pass 1: exp (stored back into acc) + row sums
    #pragma unroll
    for (int mf = 0; mf < 2; mf++) {
        #pragma unroll
        for (int h = 0; h < 2; h++) {
            int R  = wm * 32 + mf * 16 + quad + 8 * h;
            int lr = s_lrow[R];
            lrv[mf][h] = lr;
            float p = 0.0f, t = 0.0f;
            #pragma unroll
            for (int nf = 0; nf < 8; nf++) {
                #pragma unroll
                for (int j = 0; j < 2; j++) {
                    int cidx = wn * 64 + nf * 8 + 2 * qid + j;
                    float e = __expf(acc[mf][nf][2 * h + j] * INV_TEMP);
                    if (diag && cidx == R) {
                        acc[mf][nf][2 * h + j] = 0.0f;   // diagonal handled exactly
                        t += EXP_DIAG;
                    } else {
                        acc[mf][nf][2 * h + j] = e;
                        t += e;
                        if (s_lcol[cidx] == lr) p += e;
                    }
                }
            }
            p += __shfl_xor_sync(0xffffffffu, p, 1);
            p += __shfl_xor_sync(0xffffffffu, p, 2);
            t += __shfl_xor_sync(0xffffffffu, t, 1);
            t += __shfl_xor_sync(0xffffffffu, t, 2);
            if (qid == 0) {
                atomicAdd(&s_rpos[R], p);
                atomicAdd(&s_rtot[R], t);
            }
        }
    }

    // pass 2 (off-diagonal only): column sums = symmetric contributions
    if (!diag) {
        #pragma unroll
        for (int nf = 0; nf < 8; nf++) {
            #pragma unroll
            for (int j = 0; j < 2; j++) {
                int cidx = wn * 64 + nf * 8 + 2 * qid + j;
                int lc = s_lcol[cidx];
                float cp = 0.0f, ct = 0.0f;
                #pragma unroll
                for (int mf = 0; mf < 2; mf++)
                    #pragma unroll
                    for (int h = 0; h < 2; h++) {
                        float e = acc[mf][nf][2 * h + j];
                        ct += e;
                        if (lrv[mf][h] == lc) cp += e;
                    }
                // reduce across quads (lanes with same qid share column)
                cp += __shfl_xor_sync(0xffffffffu, cp, 4);
                cp += __shfl_xor_sync(0xffffffffu, cp, 8);
                cp += __shfl_xor_sync(0xffffffffu, cp, 16);
                ct += __shfl_xor_sync(0xffffffffu, ct, 4);
                ct += __shfl_xor_sync(0xffffffffu, ct, 8);
                ct += __shfl_xor_sync(0xffffffffu, ct, 16);
                if (quad == 0) {
                    atomicAdd(&s_cpos[cidx], cp);
                    atomicAdd(&s_ctot[cidx], ct);
                }
            }
        }
    }

    __syncthreads();
    if (tid < 128) {
        atomicAdd(&g_pos[rb + tid], s_rpos[tid]);
        atomicAdd(&g_tot[rb + tid], s_rtot[tid]);
    } else if (!diag) {
        int t2 = tid - 128;
        atomicAdd(&g_pos[cb + t2], s_cpos[t2]);
        atomicAdd(&g_tot[cb + t2], s_ctot[t2]);
    }
}

// ---------------------------------------------------------------------------
// Kernel 3: triplet hinge. One warp per triplet; block-reduced atomicAdd.
// ---------------------------------------------------------------------------
__global__ void trip_kernel(const float* __restrict__ emb,
                            const int* __restrict__ trips) {
    __shared__ float s_h[8];
    int warp = threadIdx.x >> 5;
    int lane = threadIdx.x & 31;
    int t = blockIdx.x * 8 + warp;
    int ia = trips[3*t + 0], ip = trips[3*t + 1], in_ = trips[3*t + 2];
    const float4* pa = (const float4*)(emb + (size_t)ia * DD);
    const float4* pp = (const float4*)(emb + (size_t)ip * DD);
    const float4* pn = (const float4*)(emb + (size_t)in_ * DD);
    float sp = 0.0f, sn = 0.0f;
    #pragma unroll
    for (int w = 0; w < 4; w++) {
        int idx = lane + w * 32;
        float4 a = pa[idx], p = pp[idx], n = pn[idx];
        float d;
        d = a.x - p.x + PD_EPSF; sp = fmaf(d, d, sp);
        d = a.y - p.y + PD_EPSF; sp = fmaf(d, d, sp);
        d = a.z - p.z + PD_EPSF; sp = fmaf(d, d, sp);
        d = a.w - p.w + PD_EPSF; sp = fmaf(d, d, sp);
        d = a.x - n.x + PD_EPSF; sn = fmaf(d, d, sn);
        d = a.y - n.y + PD_EPSF; sn = fmaf(d, d, sn);
        d = a.z - n.z + PD_EPSF; sn = fmaf(d, d, sn);
        d = a.w - n.w + PD_EPSF; sn = fmaf(d, d, sn);
    }
    #pragma unroll
    for (int o = 16; o; o >>= 1) {
        sp += __shfl_xor_sync(0xffffffffu, sp, o);
        sn += __shfl_xor_sync(0xffffffffu, sn, o);
    }
    if (lane == 0)
        s_h[warp] = fmaxf(sqrtf(sp) - sqrtf(sn) + MARGINF, 0.0f);
    __syncthreads();
    if (threadIdx.x == 0) {
        float s = s_h[0]+s_h[1]+s_h[2]+s_h[3]+s_h[4]+s_h[5]+s_h[6]+s_h[7];
        atomicAdd(&g_fin[2], s);
    }
}

// ---------------------------------------------------------------------------
// Kernel 4a: per-row contrastive loss, grid-parallel reduce into g_fin.
// ---------------------------------------------------------------------------
__global__ void fin1_kernel() {
    int r = blockIdx.x * 256 + threadIdx.x;
    float p = g_pos[r], q = g_tot[r];
    float l = 0.0f, c = 0.0f;
    if (p > 0.0f) {
        l = -__logf(p / (q + EPSF) + EPSF);
        c = 1.0f;
    }
    #pragma unroll
    for (int o = 16; o; o >>= 1) {
        l += __shfl_xor_sync(0xffffffffu, l, o);
        c += __shfl_xor_sync(0xffffffffu, c, o);
    }
    __shared__ float sl[8], sc[8];
    int warp = threadIdx.x >> 5, lane = threadIdx.x & 31;
    if (lane == 0) { sl[warp] = l; sc[warp] = c; }
    __syncthreads();
    if (threadIdx.x == 0) {
        float L = sl[0]+sl[1]+sl[2]+sl[3]+sl[4]+sl[5]+sl[6]+sl[7];
        float C = sc[0]+sc[1]+sc[2]+sc[3]+sc[4]+sc[5]+sc[6]+sc[7];
        atomicAdd(&g_fin[0], L);
        atomicAdd(&g_fin[1], C);
    }
}

// ---------------------------------------------------------------------------
// Kernel 4b: finalize (1 thread).
// ---------------------------------------------------------------------------
__global__ void fin2_kernel(float* __restrict__ out) {
    float cont = (g_fin[1] > 0.0f) ? (g_fin[0] / g_fin[1]) : 0.0f;
    float trip = g_fin[2] / (float)TT;
    out[0] = cont + TRIP_W * trip;
    out[1] = cont;
    out[2] = trip;
}

// ---------------------------------------------------------------------------
extern "C" void kernel_launch(void* const* d_in, const int* in_sizes, int n_in,
                              void* d_out, int out_size) {
    (void)in_sizes; (void)n_in; (void)out_size;
    const float* emb    = (const float*)d_in[0];
    const int*   labels = (const int*)d_in[1];
    const int*   trips  = (const int*)d_in[2];
    float*       out    = (float*)d_out;

    norm_kernel<<<NN, 128>>>(emb);
    sim_kernel<<<NTRI, 256>>>(labels);
    trip_kernel<<<TT / 8, 256>>>(emb, trips);
    fin1_kernel<<<16, 256>>>();
    fin2_kernel<<<1, 1>>>(out);
}